// round 1
// baseline (speedup 1.0000x reference)
#include <cuda_runtime.h>
#include <math.h>

#define NSAMP   4194304
#define HOP     128
#define NFFT    512
#define NH      256          // complex FFT size (real-packing trick)
#define NFRAMES 32769
#define NBINS   257
#define OUT_STRIDE (3*NBINS) // 771
#define PI_F 3.14159265358979323846f

// Scratch (no cudaMalloc allowed)
__device__ float2 g_partial[256];
__device__ float  g_c;

// ---------------------------------------------------------------------------
// Pass 1: per-block partial (sum, sumsq) over the 4.19M samples
// ---------------------------------------------------------------------------
__global__ __launch_bounds__(256) void reduce_pass1(const float* __restrict__ x) {
    __shared__ float s_sum[256];
    __shared__ float s_sq[256];
    const int tid = threadIdx.x;
    float sum = 0.f, sq = 0.f;
    const float4* x4 = (const float4*)x;
    const int n4 = NSAMP / 4;
    for (int i = blockIdx.x * 256 + tid; i < n4; i += 256 * 256) {
        float4 v = x4[i];
        sum += (v.x + v.y) + (v.z + v.w);
        sq  += (v.x*v.x + v.y*v.y) + (v.z*v.z + v.w*v.w);
    }
    s_sum[tid] = sum; s_sq[tid] = sq;
    __syncthreads();
    for (int s = 128; s > 0; s >>= 1) {
        if (tid < s) { s_sum[tid] += s_sum[tid + s]; s_sq[tid] += s_sq[tid + s]; }
        __syncthreads();
    }
    if (tid == 0) g_partial[blockIdx.x] = make_float2(s_sum[0], s_sq[0]);
}

// ---------------------------------------------------------------------------
// Pass 2: final combine in double, c = mean / std (ddof=1)
// ---------------------------------------------------------------------------
__global__ __launch_bounds__(256) void reduce_pass2() {
    __shared__ double s_sum[256];
    __shared__ double s_sq[256];
    const int tid = threadIdx.x;
    float2 p = g_partial[tid];
    s_sum[tid] = (double)p.x; s_sq[tid] = (double)p.y;
    __syncthreads();
    for (int s = 128; s > 0; s >>= 1) {
        if (tid < s) { s_sum[tid] += s_sum[tid + s]; s_sq[tid] += s_sq[tid + s]; }
        __syncthreads();
    }
    if (tid == 0) {
        double S = s_sum[0], SS = s_sq[0];
        double mean = S / (double)NSAMP;
        double var  = (SS - S * S / (double)NSAMP) / (double)(NSAMP - 1);
        g_c = (float)(mean / sqrt(var));
    }
}

// ---------------------------------------------------------------------------
// Per-bin epilogue: log-magnitude, sin(phase), cos(phase)
// sin(unwrap(phase)) == sin(phase) (unwrap adds exact multiples of 2*pi)
// ---------------------------------------------------------------------------
__device__ __forceinline__ void emit_bin(const float2* __restrict__ Z,
                                         float* __restrict__ orow, int k) {
    float2 zk = Z[k & (NH - 1)];
    float2 zc = Z[(NH - k) & (NH - 1)];
    // Xe = (Zk + conj(Zc))/2 ; Xo = -i*(Zk - conj(Zc))/2
    float xer = 0.5f * (zk.x + zc.x);
    float xei = 0.5f * (zk.y - zc.y);
    float xox = 0.5f * (zk.y + zc.y);
    float xoy = -0.5f * (zk.x - zc.x);
    float sw, cw;
    __sincosf((float)k * (-PI_F / 256.f), &sw, &cw);   // e^{-i*pi*k/256}
    float re = xer + cw * xox - sw * xoy;
    float im = xei + cw * xoy + sw * xox;

    float r2 = re * re + im * im;
    float lm, sv, cv;
    if (r2 > 0.f) {
        float inv = rsqrtf(r2);
        float mag = r2 * inv;
        lm = __logf(mag + 1e-9f);
        sv = im * inv;
        cv = re * inv;
    } else {
        lm = __logf(1e-9f);
        sv = 0.f;
        cv = 1.f;
    }
    orow[k]             = lm;
    orow[NBINS + k]     = sv;
    orow[2 * NBINS + k] = cv;
}

// ---------------------------------------------------------------------------
// STFT: one 512-sample frame per block, 128 threads.
// Real input packed into 256-pt complex FFT (Stockham radix-2, 8 stages).
// ---------------------------------------------------------------------------
__global__ __launch_bounds__(128) void stft_kernel(const float* __restrict__ audio,
                                                   float* __restrict__ out) {
    __shared__ float2 bufA[NH];
    __shared__ float2 bufB[NH];
    const int t   = blockIdx.x;
    const int tid = threadIdx.x;
    const float c = g_c;
    const int base = t * HOP - NFFT / 2;   // reflect-padded start

    // Load + reflect + normalize + Hann window; pack z[n] = x[2n] + i*x[2n+1]
    #pragma unroll
    for (int r = 0; r < 2; ++r) {
        int n  = tid + r * 128;
        int j0 = 2 * n;
        int p0 = base + j0, p1 = p0 + 1;
        if (p0 < 0) p0 = -p0; else if (p0 >= NSAMP) p0 = 2 * NSAMP - 2 - p0;
        if (p1 < 0) p1 = -p1; else if (p1 >= NSAMP) p1 = 2 * NSAMP - 2 - p1;
        float v0 = audio[p0] - c;
        float v1 = audio[p1] - c;
        // hann[j] = 0.5*(1 - cos(2*pi*j/512)) ; j/256 is exact
        float h0 = 0.5f * (1.f - cospif((float)j0       * (1.f / 256.f)));
        float h1 = 0.5f * (1.f - cospif((float)(j0 + 1) * (1.f / 256.f)));
        bufA[n] = make_float2(v0 * h0, v1 * h1);
    }
    __syncthreads();

    // 8-stage radix-2 Stockham (out-of-place ping-pong), forward (e^{-i...})
    float2* src = bufA;
    float2* dst = bufB;
    #pragma unroll
    for (int s = 0; s < 8; ++s) {
        const int Nsz = 1 << s;
        float2 a = src[tid];
        float2 b = src[tid + 128];
        int k = tid & (Nsz - 1);
        float ang = (float)k * (-PI_F / (float)Nsz);
        float sw, cw;
        __sincosf(ang, &sw, &cw);
        float tr = cw * b.x - sw * b.y;
        float ti = cw * b.y + sw * b.x;
        int d = ((tid >> s) << (s + 1)) + k;
        dst[d]       = make_float2(a.x + tr, a.y + ti);
        dst[d + Nsz] = make_float2(a.x - tr, a.y - ti);
        __syncthreads();
        float2* tmp = src; src = dst; dst = tmp;
    }
    // 'src' now holds Z[0..255]

    float* orow = out + (size_t)t * OUT_STRIDE;
    emit_bin(src, orow, tid);
    emit_bin(src, orow, tid + 128);
    if (tid == 0) emit_bin(src, orow, 256);
}

// ---------------------------------------------------------------------------
extern "C" void kernel_launch(void* const* d_in, const int* in_sizes, int n_in,
                              void* d_out, int out_size) {
    const float* audio = (const float*)d_in[0];
    float* out = (float*)d_out;
    reduce_pass1<<<256, 256>>>(audio);
    reduce_pass2<<<1, 256>>>();
    stft_kernel<<<NFRAMES, 128>>>(audio, out);
}